// round 1
// baseline (speedup 1.0000x reference)
#include <cuda_runtime.h>

typedef unsigned long long ull;

#define Bq 16
#define Cq 512
#define Nq 4096
#define Kq 64

// ---------------- scratch (static device allocations only) ----------------
__device__ float gW1[Cq][Kq];        // inv_s2, c-major k-inner (k pairs adjacent)
__device__ float gW2[Cq][Kq];        // -2*anchor*inv_s2
__device__ float gInvS[Kq][Cq];      // 1/sigma
__device__ float gCst[Kq];           // sum_c anchor^2 * inv_s2
__device__ float g_sa[(size_t)Bq*Kq*Nq];          // soft_assign scratch (if not in d_out)
__device__ float g_wx4[4][Bq][Kq][Cq];            // partial wx over 4 n-segments
__device__ float g_wsum[Bq][Kq];
__device__ float g_row[Bq][Kq];
__device__ float g_nodes[Bq][Kq][Cq];

// ---------------- f32x2 helpers ----------------
__device__ __forceinline__ ull fma2(ull a, ull b, ull c) {
    ull d;
    asm("fma.rn.f32x2 %0, %1, %2, %3;" : "=l"(d) : "l"(a), "l"(b), "l"(c));
    return d;
}
__device__ __forceinline__ ull pk2(float v) {
    ull d; unsigned r = __float_as_uint(v);
    asm("mov.b64 %0, {%1, %1};" : "=l"(d) : "r"(r));
    return d;
}
__device__ __forceinline__ float2 up2(ull a) {
    unsigned x, y;
    asm("mov.b64 {%0, %1}, %2;" : "=r"(x), "=r"(y) : "l"(a));
    return make_float2(__uint_as_float(x), __uint_as_float(y));
}

// ---------------- prep: sigma, weights, const ----------------
__global__ void prep_kernel(const float* __restrict__ anchor,
                            const float* __restrict__ sraw) {
    const int k = blockIdx.x;       // 64 blocks
    const int tid = threadIdx.x;    // 256 threads
    float part = 0.f;
#pragma unroll
    for (int j = 0; j < 2; ++j) {
        int c = tid + j * 256;
        float sr = sraw[k * Cq + c];
        float sg = 1.f / (1.f + __expf(-sr));
        float a  = anchor[k * Cq + c];
        float i2 = 1.f / (sg * sg);
        gW1[c][k] = i2;
        gW2[c][k] = -2.f * a * i2;
        gInvS[k][c] = 1.f / sg;
        part += a * a * i2;
    }
#pragma unroll
    for (int off = 16; off; off >>= 1) part += __shfl_xor_sync(0xffffffffu, part, off);
    __shared__ float red[8];
    if ((tid & 31) == 0) red[tid >> 5] = part;
    __syncthreads();
    if (tid == 0) {
        float s = 0.f;
#pragma unroll
        for (int i = 0; i < 8; ++i) s += red[i];
        gCst[k] = s;
    }
}

// ---------------- phase 1: distances + softmax over K ----------------
// grid 256 (16 n-tiles per b), block 256, thread = one n, 64 accumulators as 32 f32x2
__global__ __launch_bounds__(256, 2)
void phase1_kernel(const float* __restrict__ x, float* __restrict__ sa) {
    __shared__ float sW1[32][64];
    __shared__ float sW2[32][64];
    __shared__ float sC[64];
    const int tid = threadIdx.x;
    const int b = blockIdx.x >> 4;
    const int n = ((blockIdx.x & 15) << 8) + tid;
    const float* xb = x + (size_t)b * Cq * Nq + n;
    if (tid < 64) sC[tid] = gCst[tid];

    ull acc[32];
#pragma unroll
    for (int i = 0; i < 32; ++i) acc[i] = 0ull;

    for (int c0 = 0; c0 < Cq; c0 += 32) {
        __syncthreads();
#pragma unroll
        for (int i = 0; i < 8; ++i) {
            int idx = tid + i * 256;
            int r = idx >> 6, cc = idx & 63;
            sW1[r][cc] = gW1[c0 + r][cc];
            sW2[r][cc] = gW2[c0 + r][cc];
        }
        __syncthreads();
        float xr[32];
#pragma unroll
        for (int cc = 0; cc < 32; ++cc) xr[cc] = xb[(size_t)(c0 + cc) * Nq];
#pragma unroll 4
        for (int cc = 0; cc < 32; ++cc) {
            float xv = xr[cc];
            ull X  = pk2(xv);
            ull X2 = pk2(xv * xv);
            const float* w1p = &sW1[cc][0];
            const float* w2p = &sW2[cc][0];
#pragma unroll
            for (int kk = 0; kk < 32; ++kk) {
                ull w1 = *reinterpret_cast<const ull*>(w1p + 2 * kk);
                acc[kk] = fma2(X2, w1, acc[kk]);
                ull w2 = *reinterpret_cast<const ull*>(w2p + 2 * kk);
                acc[kk] = fma2(X, w2, acc[kk]);
            }
        }
    }
    // softmax over 64 nodes (logit = -0.5*d2)
    float e[64];
#pragma unroll
    for (int kk = 0; kk < 32; ++kk) {
        float2 v = up2(acc[kk]);
        e[2 * kk]     = v.x + sC[2 * kk];
        e[2 * kk + 1] = v.y + sC[2 * kk + 1];
    }
    float dmin = e[0];
#pragma unroll
    for (int k = 1; k < 64; ++k) dmin = fminf(dmin, e[k]);
    float s = 0.f;
#pragma unroll
    for (int k = 0; k < 64; ++k) {
        float t = __expf(-0.5f * (e[k] - dmin));
        e[k] = t;
        s += t;
    }
    float r = 1.f / s;
    float* sp = sa + (size_t)b * Kq * Nq + n;
#pragma unroll
    for (int k = 0; k < 64; ++k) sp[(size_t)k * Nq] = e[k] * r;
}

// ---------------- w_sum ----------------
__global__ void wsum_kernel(const float* __restrict__ sa) {
    const int bk = blockIdx.x;      // 1024 blocks
    const int tid = threadIdx.x;    // 256 threads
    const float4* row = reinterpret_cast<const float4*>(sa + (size_t)bk * Nq);
    float s = 0.f;
#pragma unroll
    for (int i = 0; i < 4; ++i) {
        float4 v = row[tid + i * 256];
        s += (v.x + v.y) + (v.z + v.w);
    }
#pragma unroll
    for (int off = 16; off; off >>= 1) s += __shfl_xor_sync(0xffffffffu, s, off);
    __shared__ float red[8];
    if ((tid & 31) == 0) red[tid >> 5] = s;
    __syncthreads();
    if (tid == 0) {
        float t = 0.f;
#pragma unroll
        for (int i = 0; i < 8; ++i) t += red[i];
        g_wsum[bk >> 6][bk & 63] = t;
    }
}

// ---------------- phase 2: wx[b,k,c] = sum_n sa[b,k,n]*x[b,c,n] ----------------
// grid (8 c-tiles, 16 b, 4 n-segs), block 128; thread tiles 4c x 8k (f32x2 over k)
__global__ __launch_bounds__(128)
void phase2_kernel(const float* __restrict__ x, const float* __restrict__ sa) {
    __shared__ float xs[64][65];   // [c][n], pad 65 -> conflict-free strided-c reads
    __shared__ float ws[64][66];   // [n][k], pad 66 keeps 8B align for k-pairs
    const int tid = threadIdx.x;
    const int ct = blockIdx.x;
    const int b  = blockIdx.y;
    const int seg = blockIdx.z;
    const int c0 = ct << 6;
    const int nb = seg << 10;
    const int cg = tid & 15;       // c = c0 + cg + 16*ci
    const int kg = tid >> 4;
    const int k8 = kg << 3;        // 8 k's per thread (4 pairs)
    ull acc[4][4];
#pragma unroll
    for (int i = 0; i < 4; ++i)
#pragma unroll
        for (int j = 0; j < 4; ++j) acc[i][j] = 0ull;

    const float* xb = x + ((size_t)b * Cq + c0) * Nq + nb;
    const float* sb = sa + (size_t)b * Kq * Nq + nb;

    for (int nc = 0; nc < 16; ++nc) {
        const int nn = nc << 6;
        __syncthreads();
#pragma unroll
        for (int i = 0; i < 8; ++i) {
            int idx = tid + i * 128;
            int rr = idx >> 4, q = idx & 15;
            float4 v = *reinterpret_cast<const float4*>(xb + (size_t)rr * Nq + nn + (q << 2));
            xs[rr][4 * q + 0] = v.x;
            xs[rr][4 * q + 1] = v.y;
            xs[rr][4 * q + 2] = v.z;
            xs[rr][4 * q + 3] = v.w;
        }
#pragma unroll
        for (int i = 0; i < 32; ++i) {
            int idx = tid + i * 128;
            int kr = idx >> 6, q = idx & 63;
            ws[q][kr] = sb[(size_t)kr * Nq + nn + q];
        }
        __syncthreads();
#pragma unroll 8
        for (int n = 0; n < 64; ++n) {
            ull X[4];
#pragma unroll
            for (int ci = 0; ci < 4; ++ci) X[ci] = pk2(xs[cg + 16 * ci][n]);
#pragma unroll
            for (int kk = 0; kk < 4; ++kk) {
                ull w = *reinterpret_cast<const ull*>(&ws[n][k8 + 2 * kk]);
#pragma unroll
                for (int ci = 0; ci < 4; ++ci)
                    acc[ci][kk] = fma2(X[ci], w, acc[ci][kk]);
            }
        }
    }
#pragma unroll
    for (int ci = 0; ci < 4; ++ci) {
        int c = c0 + cg + 16 * ci;
#pragma unroll
        for (int kk = 0; kk < 4; ++kk) {
            float2 v = up2(acc[ci][kk]);
            g_wx4[seg][b][k8 + 2 * kk][c]     = v.x;
            g_wx4[seg][b][k8 + 2 * kk + 1][c] = v.y;
        }
    }
}

// ---------------- phase 3: nodes + per-row l2norm ----------------
__global__ void phase3_kernel(const float* __restrict__ anchor) {
    const int bk = blockIdx.x;     // 1024 blocks
    const int b = bk >> 6, k = bk & 63;
    const int tid = threadIdx.x;   // 128 threads
    const float wsv = g_wsum[b][k];
    const float invw = 1.f / (wsv + 1e-9f);
    float t[4];
    float ssq = 0.f;
#pragma unroll
    for (int j = 0; j < 4; ++j) {
        int c = tid + j * 128;
        float wx = g_wx4[0][b][k][c] + g_wx4[1][b][k][c]
                 + g_wx4[2][b][k][c] + g_wx4[3][b][k][c];
        float nd = (wx - wsv * anchor[k * Cq + c]) * gInvS[k][c] * invw;
        t[j] = nd;
        ssq += nd * nd;
    }
#pragma unroll
    for (int off = 16; off; off >>= 1) ssq += __shfl_xor_sync(0xffffffffu, ssq, off);
    __shared__ float red[4];
    __shared__ float totsh;
    if ((tid & 31) == 0) red[tid >> 5] = ssq;
    __syncthreads();
    if (tid == 0) totsh = red[0] + red[1] + red[2] + red[3];
    __syncthreads();
    float total = totsh;
    float scale = 1.f / fmaxf(sqrtf(total), 1e-12f);
#pragma unroll
    for (int j = 0; j < 4; ++j) {
        int c = tid + j * 128;
        g_nodes[b][k][c] = t[j] * scale;
    }
    if (tid == 0) g_row[b][k] = total * scale * scale;
}

// ---------------- phase 4: global l2norm + output ----------------
__global__ void phase4_kernel(float* __restrict__ outflat) {
    const int b = blockIdx.x;      // 16 blocks
    const int tid = threadIdx.x;   // 256 threads
    __shared__ float red[64];
    __shared__ float gsh;
    if (tid < 64) red[tid] = g_row[b][tid];
    __syncthreads();
    if (tid == 0) {
        float s = 0.f;
#pragma unroll
        for (int i = 0; i < 64; ++i) s += red[i];
        gsh = 1.f / fmaxf(sqrtf(s), 1e-12f);
    }
    __syncthreads();
    float g = gsh;
    const float* np = &g_nodes[b][0][0];
    float* op = outflat + (size_t)b * Kq * Cq;
    for (int i = tid; i < Kq * Cq; i += 256) op[i] = np[i] * g;
}

// ---------------- launch ----------------
extern "C" void kernel_launch(void* const* d_in, const int* in_sizes, int n_in,
                              void* d_out, int out_size) {
    const float* x      = (const float*)d_in[0];
    const float* anchor = (const float*)d_in[1];
    const float* sraw   = (const float*)d_in[2];
    float* outf = (float*)d_out;

    const int FLAT = Bq * Cq * Kq;      // 524288
    const int SA   = Bq * Kq * Nq;      // 4194304

    float* sa_dev = nullptr;
    cudaGetSymbolAddress((void**)&sa_dev, g_sa);
    float* nodes_dev = nullptr;
    cudaGetSymbolAddress((void**)&nodes_dev, g_nodes);

    float* sa_ptr;
    float* flat_ptr;
    if (out_size == FLAT) {                // flat only
        flat_ptr = outf;
        sa_ptr = sa_dev;
    } else if (out_size == SA) {           // soft_assign only
        sa_ptr = outf;
        flat_ptr = nodes_dev;              // scaled in place, discarded
    } else {                               // both, tuple order (flat, soft_assign)
        flat_ptr = outf;
        sa_ptr = outf + FLAT;
    }

    prep_kernel<<<Kq, 256>>>(anchor, sraw);
    phase1_kernel<<<Bq * (Nq / 256), 256>>>(x, sa_ptr);
    wsum_kernel<<<Bq * Kq, 256>>>(sa_ptr);
    phase2_kernel<<<dim3(Cq / 64, Bq, 4), 128>>>(x, sa_ptr);
    phase3_kernel<<<Bq * Kq, 128>>>(anchor);
    phase4_kernel<<<Bq, 256>>>(flat_ptr);
}

// round 2
// speedup vs baseline: 1.0863x; 1.0863x over previous
#include <cuda_runtime.h>

typedef unsigned long long ull;

#define Bq 16
#define Cq 512
#define Nq 4096
#define Kq 64

// ---------------- scratch (static device allocations only) ----------------
__device__ ull   gW1d[Cq][Kq];       // inv_s2 duplicated as f32x2 pairs
__device__ ull   gW2d[Cq][Kq];       // -2*anchor*inv_s2 duplicated
__device__ float gInvS[Kq][Cq];      // 1/sigma
__device__ float gCst[Kq];           // sum_c anchor^2 * inv_s2
__device__ float g_sa[(size_t)Bq*Kq*Nq];          // soft_assign scratch
__device__ float g_wx[8][Bq][Kq][Cq];             // partial wx over 8 n-segments
__device__ float g_wsum[Bq][Kq];
__device__ float g_row[Bq][Kq];
__device__ float g_nodes[Bq][Kq][Cq];

// ---------------- f32x2 helpers ----------------
__device__ __forceinline__ ull fma2(ull a, ull b, ull c) {
    ull d;
    asm("fma.rn.f32x2 %0, %1, %2, %3;" : "=l"(d) : "l"(a), "l"(b), "l"(c));
    return d;
}
__device__ __forceinline__ ull mul2(ull a, ull b) {
    ull d;
    asm("mul.rn.f32x2 %0, %1, %2;" : "=l"(d) : "l"(a), "l"(b));
    return d;
}
__device__ __forceinline__ ull add2(ull a, ull b) {
    ull d;
    asm("add.rn.f32x2 %0, %1, %2;" : "=l"(d) : "l"(a), "l"(b));
    return d;
}
__device__ __forceinline__ ull pk2(float v) {
    ull d; unsigned r = __float_as_uint(v);
    asm("mov.b64 %0, {%1, %1};" : "=l"(d) : "r"(r));
    return d;
}
__device__ __forceinline__ float2 up2(ull a) {
    unsigned x, y;
    asm("mov.b64 {%0, %1}, %2;" : "=r"(x), "=r"(y) : "l"(a));
    return make_float2(__uint_as_float(x), __uint_as_float(y));
}

// ---------------- prep: sigma, duplicated packed weights, const ----------------
__global__ void prep_kernel(const float* __restrict__ anchor,
                            const float* __restrict__ sraw) {
    const int k = blockIdx.x;       // 64 blocks
    const int tid = threadIdx.x;    // 256 threads
    float part = 0.f;
#pragma unroll
    for (int j = 0; j < 2; ++j) {
        int c = tid + j * 256;
        float sr = sraw[k * Cq + c];
        float sg = 1.f / (1.f + __expf(-sr));
        float a  = anchor[k * Cq + c];
        float i2 = 1.f / (sg * sg);
        gW1d[c][k] = pk2(i2);
        gW2d[c][k] = pk2(-2.f * a * i2);
        gInvS[k][c] = 1.f / sg;
        part += a * a * i2;
    }
#pragma unroll
    for (int off = 16; off; off >>= 1) part += __shfl_xor_sync(0xffffffffu, part, off);
    __shared__ float red[8];
    if ((tid & 31) == 0) red[tid >> 5] = part;
    __syncthreads();
    if (tid == 0) {
        float s = 0.f;
#pragma unroll
        for (int i = 0; i < 8; ++i) s += red[i];
        gCst[k] = s;
    }
}

// ---------------- phase 1: distances + softmax over K ----------------
// grid 512 (32 n-tiles x 16 b), block 128. Tile: 128 n x 64 k, C chunked by 32.
// Thread tile: 8 n (as 4 f32x2 pairs) x 8 k -> 32 ull accs.
__global__ __launch_bounds__(128, 4)
void phase1_kernel(const float* __restrict__ x, float* __restrict__ sa) {
    __shared__ union SMem {
        struct { float xs[32][128]; ull w1[32][64]; ull w2[32][64]; } m; // 48KB
        float d2[64][130];                                              // 33.3KB
    } sm;
    const int tid = threadIdx.x;
    const int ng = tid & 15;        // 8 n each
    const int kg = tid >> 4;        // 8 k each
    const int k8 = kg << 3;
    const int b  = blockIdx.x >> 5;
    const int nb = (blockIdx.x & 31) << 7;
    const float* xb = x + (size_t)b * Cq * Nq + nb;

    ull acc[4][8];
#pragma unroll
    for (int i = 0; i < 4; ++i)
#pragma unroll
        for (int j = 0; j < 8; ++j) acc[i][j] = 0ull;

    for (int c0 = 0; c0 < Cq; c0 += 32) {
        __syncthreads();
        // x tile: 32c x 128n = 1024 float4, 8 per thread
#pragma unroll
        for (int i = 0; i < 8; ++i) {
            int idx = tid + (i << 7);
            int cc = idx >> 5, q = idx & 31;
            *(float4*)&sm.m.xs[cc][q << 2] =
                *(const float4*)(xb + (size_t)(c0 + cc) * Nq + (q << 2));
        }
        // dup weights: 32c x 64k ull = 1024 ull2 each, 8 per thread each
#pragma unroll
        for (int i = 0; i < 8; ++i) {
            int idx = tid + (i << 7);
            int cc = idx >> 5, q = idx & 31;
            *(ulonglong2*)&sm.m.w1[cc][q << 1] = *(const ulonglong2*)&gW1d[c0 + cc][q << 1];
            *(ulonglong2*)&sm.m.w2[cc][q << 1] = *(const ulonglong2*)&gW2d[c0 + cc][q << 1];
        }
        __syncthreads();
#pragma unroll 2
        for (int cc = 0; cc < 32; ++cc) {
            ulonglong2 xa = *(const ulonglong2*)&sm.m.xs[cc][ng << 3];
            ulonglong2 xc = *(const ulonglong2*)&sm.m.xs[cc][(ng << 3) + 4];
            ull xp[4] = { xa.x, xa.y, xc.x, xc.y };
            ull xq[4];
#pragma unroll
            for (int i = 0; i < 4; ++i) xq[i] = mul2(xp[i], xp[i]);
            const ulonglong2* w1p = (const ulonglong2*)&sm.m.w1[cc][k8];
            const ulonglong2* w2p = (const ulonglong2*)&sm.m.w2[cc][k8];
#pragma unroll
            for (int kk = 0; kk < 4; ++kk) {
                ulonglong2 w1 = w1p[kk];
                ulonglong2 w2 = w2p[kk];
#pragma unroll
                for (int np = 0; np < 4; ++np) {
                    acc[np][2 * kk]     = fma2(xq[np], w1.x, acc[np][2 * kk]);
                    acc[np][2 * kk]     = fma2(xp[np], w2.x, acc[np][2 * kk]);
                    acc[np][2 * kk + 1] = fma2(xq[np], w1.y, acc[np][2 * kk + 1]);
                    acc[np][2 * kk + 1] = fma2(xp[np], w2.y, acc[np][2 * kk + 1]);
                }
            }
        }
    }
    __syncthreads();
    // epilogue: + const, stage d2[k][n] in smem
#pragma unroll
    for (int kk = 0; kk < 8; ++kk) {
        int k = k8 + kk;
        ull cp = pk2(__ldg(&gCst[k]));
#pragma unroll
        for (int np = 0; np < 4; ++np) {
            *(ull*)&sm.d2[k][(ng << 3) + (np << 1)] = add2(acc[np][kk], cp);
        }
    }
    __syncthreads();
    // softmax: one thread per n
    {
        const int n = tid;
        float e[64];
#pragma unroll
        for (int k = 0; k < 64; ++k) e[k] = sm.d2[k][n];
        float mn = e[0];
#pragma unroll
        for (int k = 1; k < 64; ++k) mn = fminf(mn, e[k]);
        float s = 0.f;
#pragma unroll
        for (int k = 0; k < 64; ++k) {
            float t = __expf(-0.5f * (e[k] - mn));
            e[k] = t;
            s += t;
        }
        float r = 1.f / s;
        float* sp = sa + (size_t)b * Kq * Nq + nb + n;
#pragma unroll
        for (int k = 0; k < 64; ++k) sp[(size_t)k * Nq] = e[k] * r;
    }
}

// ---------------- w_sum ----------------
__global__ void wsum_kernel(const float* __restrict__ sa) {
    const int bk = blockIdx.x;      // 1024 blocks
    const int tid = threadIdx.x;    // 256 threads
    const float4* row = reinterpret_cast<const float4*>(sa + (size_t)bk * Nq);
    float s = 0.f;
#pragma unroll
    for (int i = 0; i < 4; ++i) {
        float4 v = row[tid + i * 256];
        s += (v.x + v.y) + (v.z + v.w);
    }
#pragma unroll
    for (int off = 16; off; off >>= 1) s += __shfl_xor_sync(0xffffffffu, s, off);
    __shared__ float red[8];
    if ((tid & 31) == 0) red[tid >> 5] = s;
    __syncthreads();
    if (tid == 0) {
        float t = 0.f;
#pragma unroll
        for (int i = 0; i < 8; ++i) t += red[i];
        g_wsum[bk >> 6][bk & 63] = t;
    }
}

// ---------------- phase 2: wx[b,k,c] = sum_n sa[b,k,n]*x[b,c,n] ----------------
// grid (4 ctiles, 16 b, 8 segs), block 128. Block tile 128c x 64k, 512 n per seg
// chunked by 32. Thread tile 8c x 8k, f32x2 paired along reduction dim n.
__global__ __launch_bounds__(128)
void phase2_kernel(const float* __restrict__ x, const float* __restrict__ sa) {
    __shared__ float xs[128][32];   // swizzled: col4' = q ^ ((c>>3)&7)
    __shared__ float ws[64][32];    // swizzled: col4' = q ^ ((k>>3)&7)
    const int tid = threadIdx.x;
    const int cg = tid & 15;        // 8 c each
    const int kg = tid >> 4;        // 8 k each
    const int c0 = (int)blockIdx.x << 7;
    const int b  = blockIdx.y;
    const int seg = blockIdx.z;
    const int n0 = seg << 9;
    const float* xb = x  + ((size_t)b * Cq + c0) * Nq + n0;
    const float* sb = sa + (size_t)b * Kq * Nq + n0;
    const int swc = cg & 7;

    ull acc[8][8];
#pragma unroll
    for (int i = 0; i < 8; ++i)
#pragma unroll
        for (int j = 0; j < 8; ++j) acc[i][j] = 0ull;

    for (int ch = 0; ch < 16; ++ch) {
        const int nn = ch << 5;
        __syncthreads();
        // xs: 128c x 32n = 1024 float4, 8 per thread (swizzled store)
#pragma unroll
        for (int i = 0; i < 8; ++i) {
            int idx = tid + (i << 7);
            int c = idx >> 3, q = idx & 7;
            int sw = (c >> 3) & 7;
            *(float4*)&xs[c][(q ^ sw) << 2] =
                *(const float4*)(xb + (size_t)c * Nq + nn + (q << 2));
        }
        // ws: 64k x 32n = 512 float4, 4 per thread
#pragma unroll
        for (int i = 0; i < 4; ++i) {
            int idx = tid + (i << 7);
            int k = idx >> 3, q = idx & 7;
            int sw = (k >> 3) & 7;
            *(float4*)&ws[k][(q ^ sw) << 2] =
                *(const float4*)(sb + (size_t)k * Nq + nn + (q << 2));
        }
        __syncthreads();
#pragma unroll 2
        for (int j = 0; j < 8; ++j) {   // 4 n (2 pairs) per step
            ull xr[8][2];
#pragma unroll
            for (int ci = 0; ci < 8; ++ci) {
                ulonglong2 v = *(const ulonglong2*)&xs[(cg << 3) + ci][(j ^ swc) << 2];
                xr[ci][0] = v.x; xr[ci][1] = v.y;
            }
#pragma unroll
            for (int kk = 0; kk < 8; ++kk) {
                ulonglong2 w = *(const ulonglong2*)&ws[(kg << 3) + kk][(j ^ kg) << 2];
#pragma unroll
                for (int ci = 0; ci < 8; ++ci) {
                    acc[ci][kk] = fma2(xr[ci][0], w.x, acc[ci][kk]);
                    acc[ci][kk] = fma2(xr[ci][1], w.y, acc[ci][kk]);
                }
            }
        }
    }
    // epilogue: horizontal pair-add (fixed order), store partials
#pragma unroll
    for (int kk = 0; kk < 8; ++kk) {
        int k = (kg << 3) + kk;
        float o[8];
#pragma unroll
        for (int ci = 0; ci < 8; ++ci) {
            float2 v = up2(acc[ci][kk]);
            o[ci] = v.x + v.y;
        }
        float* dst = &g_wx[seg][b][k][c0 + (cg << 3)];
        *(float4*)dst       = make_float4(o[0], o[1], o[2], o[3]);
        *(float4*)(dst + 4) = make_float4(o[4], o[5], o[6], o[7]);
    }
}

// ---------------- phase 3: nodes + per-row l2norm ----------------
__global__ void phase3_kernel(const float* __restrict__ anchor) {
    const int bk = blockIdx.x;     // 1024 blocks
    const int b = bk >> 6, k = bk & 63;
    const int tid = threadIdx.x;   // 128 threads
    const float wsv = g_wsum[b][k];
    const float invw = 1.f / (wsv + 1e-9f);
    float t[4];
    float ssq = 0.f;
#pragma unroll
    for (int j = 0; j < 4; ++j) {
        int c = tid + j * 128;
        float wx = 0.f;
#pragma unroll
        for (int s = 0; s < 8; ++s) wx += g_wx[s][b][k][c];
        float nd = (wx - wsv * anchor[k * Cq + c]) * gInvS[k][c] * invw;
        t[j] = nd;
        ssq += nd * nd;
    }
#pragma unroll
    for (int off = 16; off; off >>= 1) ssq += __shfl_xor_sync(0xffffffffu, ssq, off);
    __shared__ float red[4];
    __shared__ float totsh;
    if ((tid & 31) == 0) red[tid >> 5] = ssq;
    __syncthreads();
    if (tid == 0) totsh = red[0] + red[1] + red[2] + red[3];
    __syncthreads();
    float total = totsh;
    float scale = 1.f / fmaxf(sqrtf(total), 1e-12f);
#pragma unroll
    for (int j = 0; j < 4; ++j) {
        int c = tid + j * 128;
        g_nodes[b][k][c] = t[j] * scale;
    }
    if (tid == 0) g_row[b][k] = total * scale * scale;
}

// ---------------- phase 4: global l2norm + output ----------------
__global__ void phase4_kernel(float* __restrict__ outflat) {
    const int b = blockIdx.x;      // 16 blocks
    const int tid = threadIdx.x;   // 256 threads
    __shared__ float red[64];
    __shared__ float gsh;
    if (tid < 64) red[tid] = g_row[b][tid];
    __syncthreads();
    if (tid == 0) {
        float s = 0.f;
#pragma unroll
        for (int i = 0; i < 64; ++i) s += red[i];
        gsh = 1.f / fmaxf(sqrtf(s), 1e-12f);
    }
    __syncthreads();
    float g = gsh;
    const float* np = &g_nodes[b][0][0];
    float* op = outflat + (size_t)b * Kq * Cq;
    for (int i = tid; i < Kq * Cq; i += 256) op[i] = np[i] * g;
}

// ---------------- launch ----------------
extern "C" void kernel_launch(void* const* d_in, const int* in_sizes, int n_in,
                              void* d_out, int out_size) {
    const float* x      = (const float*)d_in[0];
    const float* anchor = (const float*)d_in[1];
    const float* sraw   = (const float*)d_in[2];
    float* outf = (float*)d_out;

    const int FLAT = Bq * Cq * Kq;      // 524288
    const int SA   = Bq * Kq * Nq;      // 4194304

    float* sa_dev = nullptr;
    cudaGetSymbolAddress((void**)&sa_dev, g_sa);
    float* nodes_dev = nullptr;
    cudaGetSymbolAddress((void**)&nodes_dev, g_nodes);

    float* sa_ptr;
    float* flat_ptr;
    if (out_size == FLAT) {                // flat only
        flat_ptr = outf;
        sa_ptr = sa_dev;
    } else if (out_size == SA) {           // soft_assign only
        sa_ptr = outf;
        flat_ptr = nodes_dev;
    } else {                               // both: (flat, soft_assign)
        flat_ptr = outf;
        sa_ptr = outf + FLAT;
    }

    prep_kernel<<<Kq, 256>>>(anchor, sraw);
    phase1_kernel<<<Bq * (Nq / 128), 128>>>(x, sa_ptr);
    wsum_kernel<<<Bq * Kq, 256>>>(sa_ptr);
    phase2_kernel<<<dim3(Cq / 128, Bq, 8), 128>>>(x, sa_ptr);
    phase3_kernel<<<Bq * Kq, 128>>>(anchor);
    phase4_kernel<<<Bq, 256>>>(flat_ptr);
}

// round 6
// speedup vs baseline: 1.2804x; 1.1786x over previous
#include <cuda_runtime.h>
#include <cstdint>

#define Bq 16
#define Cq 512
#define Nq 4096
#define Kq 64

// ================= scratch (static device allocations only) =================
__device__ float2 gWh2[64][512];      // per-chunk W-hi images: [chunk][k*8+pp] = (W1h, W2h)
__device__ float2 gWl2[64][512];      // W-lo images
__device__ float gInvS[Kq][Cq];
__device__ float gCst[Kq];
__device__ float g_sa[(size_t)Bq*Kq*Nq];
__device__ float g_wx8[8][Bq][Kq][Cq];
__device__ float g_wsum[Bq][Kq];
__device__ float g_row[Bq][Kq];
__device__ float g_nodes[Bq][Kq][Cq];

// ================= helpers =================
__device__ __forceinline__ float tf32hi(float v) {
    return __uint_as_float(__float_as_uint(v) & 0xFFFFE000u);
}
// 3-bit pair-swizzle keyed on row bits 1..3
__device__ __forceinline__ int swz(int row) {
    return (((row >> 1) & 1) << 2) | (((row >> 2) & 1) << 1) | ((row >> 3) & 1);
}
__device__ __forceinline__ void mma8(float* d, const unsigned* a, const unsigned* b) {
    asm volatile(
        "mma.sync.aligned.m16n8k8.row.col.f32.tf32.tf32.f32 "
        "{%0,%1,%2,%3}, {%4,%5,%6,%7}, {%8,%9}, {%0,%1,%2,%3};"
        : "+f"(d[0]), "+f"(d[1]), "+f"(d[2]), "+f"(d[3])
        : "r"(a[0]), "r"(a[1]), "r"(a[2]), "r"(a[3]), "r"(b[0]), "r"(b[1]));
}

// smem per buffer: A-hi [256 rows][8 float2], A-lo, B-hi [64][8 float2], B-lo
#define BUF     40960
#define OFF_FH  0
#define OFF_FL  16384
#define OFF_WH  32768
#define OFF_WL  36864
#define P_SMEM  81920

// one 2-step chunk (16 reduction slots), warp tile 32(row) x 64(col), 3xTF32
__device__ __forceinline__ void gemm_chunk(const char* bufp, int rowbase, int g, int q,
                                           float acc[2][8][4]) {
    const float2* fh = (const float2*)(bufp + OFF_FH);
    const float2* fl = (const float2*)(bufp + OFF_FL);
    const float2* wh = (const float2*)(bufp + OFF_WH);
    const float2* wl = (const float2*)(bufp + OFF_WL);
#pragma unroll
    for (int s = 0; s < 2; ++s) {
        const int p = (s << 2) + q;
        unsigned ah[2][4], al[2][4];
#pragma unroll
        for (int i = 0; i < 2; ++i) {
            int r0 = rowbase + (i << 4) + g;
            int r1 = r0 + 8;
            float2 t0 = fh[r0 * 8 + (p ^ swz(r0))];
            float2 t1 = fh[r1 * 8 + (p ^ swz(r1))];
            ah[i][0] = __float_as_uint(t0.x); ah[i][2] = __float_as_uint(t0.y);
            ah[i][1] = __float_as_uint(t1.x); ah[i][3] = __float_as_uint(t1.y);
            float2 u0 = fl[r0 * 8 + (p ^ swz(r0))];
            float2 u1 = fl[r1 * 8 + (p ^ swz(r1))];
            al[i][0] = __float_as_uint(u0.x); al[i][2] = __float_as_uint(u0.y);
            al[i][1] = __float_as_uint(u1.x); al[i][3] = __float_as_uint(u1.y);
        }
#pragma unroll
        for (int j = 0; j < 8; ++j) {
            int k = (j << 3) + g;
            float2 bhv = wh[k * 8 + (p ^ swz(k))];
            float2 blv = wl[k * 8 + (p ^ swz(k))];
            unsigned bh[2] = { __float_as_uint(bhv.x), __float_as_uint(bhv.y) };
            unsigned bl[2] = { __float_as_uint(blv.x), __float_as_uint(blv.y) };
#pragma unroll
            for (int i = 0; i < 2; ++i) {
                mma8(acc[i][j], ah[i], bh);
                mma8(acc[i][j], ah[i], bl);
                mma8(acc[i][j], al[i], bh);
            }
        }
    }
}

// ================= prep: sigma, W images, const =================
__global__ void prep_kernel(const float* __restrict__ anchor,
                            const float* __restrict__ sraw) {
    const int k = blockIdx.x;       // 64
    const int tid = threadIdx.x;    // 256
    float part = 0.f;
#pragma unroll
    for (int j = 0; j < 2; ++j) {
        int c = tid + j * 256;
        float sr = sraw[k * Cq + c];
        float sg = 1.f / (1.f + __expf(-sr));
        float a  = anchor[k * Cq + c];
        float i2 = 1.f / (sg * sg);
        float w2 = -2.f * a * i2;
        gInvS[k][c] = 1.f / sg;
        part += a * a * i2;
        int ch = c >> 3, p = c & 7;
        int pp = p ^ swz(k);
        float i2h = tf32hi(i2), w2h = tf32hi(w2);
        gWh2[ch][k * 8 + pp] = make_float2(i2h, w2h);
        gWl2[ch][k * 8 + pp] = make_float2(i2 - i2h, w2 - w2h);
    }
#pragma unroll
    for (int off = 16; off; off >>= 1) part += __shfl_xor_sync(0xffffffffu, part, off);
    __shared__ float red[8];
    if ((tid & 31) == 0) red[tid >> 5] = part;
    __syncthreads();
    if (tid == 0) {
        float s = 0.f;
#pragma unroll
        for (int i = 0; i < 8; ++i) s += red[i];
        gCst[k] = s;
    }
}

// ================= phase 1: distance GEMM (3xTF32 mma) + softmax =================
// block = (n-tile 256, b). warp tile 32n x 64k. 64 chunks of 8 c (16 c2 slots).
__global__ __launch_bounds__(256, 2)
void phase1_kernel(const float* __restrict__ x, float* __restrict__ sa) {
    extern __shared__ char smem[];
    __shared__ float cst[64];
    const int tid = threadIdx.x;
    const int w = tid >> 5, lane = tid & 31;
    const int g = lane >> 2, q = lane & 3;
    const int n0w = w << 5;
    const int b  = blockIdx.y;
    const int n0 = blockIdx.x << 8;
    const float* xb = x + (size_t)b * Cq * Nq + n0;
    if (tid < 64) cst[tid] = gCst[tid];

    float acc[2][8][4];
#pragma unroll
    for (int i = 0; i < 2; ++i)
#pragma unroll
        for (int j = 0; j < 8; ++j)
#pragma unroll
            for (int e = 0; e < 4; ++e) acc[i][j][e] = 0.f;

    const int sz_n = swz(tid);
    auto fill = [&](int ch, int buf) {
        char* bp = smem + buf * BUF;
        ((float4*)(bp + OFF_WH))[tid] = ((const float4*)&gWh2[ch][0])[tid];
        ((float4*)(bp + OFF_WL))[tid] = ((const float4*)&gWl2[ch][0])[tid];
        float2* fh = (float2*)(bp + OFF_FH);
        float2* fl = (float2*)(bp + OFF_FL);
        const float* xp = xb + (size_t)(ch << 3) * Nq + tid;
#pragma unroll
        for (int cl = 0; cl < 8; ++cl) {
            float v = xp[(size_t)cl * Nq];
            float v2 = v * v;
            float vh = tf32hi(v),  vl = v - vh;
            float qh = tf32hi(v2), ql = v2 - qh;
            int pp = cl ^ sz_n;
            fh[tid * 8 + pp] = make_float2(qh, vh);   // slot q = x^2, slot q+4 = x
            fl[tid * 8 + pp] = make_float2(ql, vl);
        }
    };

    fill(0, 0);
    __syncthreads();
    for (int ch = 0; ; ++ch) {
        if (ch + 1 < 64) fill(ch + 1, (ch + 1) & 1);
        gemm_chunk(smem + (ch & 1) * BUF, n0w, g, q, acc);
        if (ch + 1 == 64) break;
        __syncthreads();
    }
    __syncthreads();

    // stage d2 in smem (overlays buffers)
    float* d2 = (float*)smem;
#pragma unroll
    for (int i = 0; i < 2; ++i) {
        int r0 = n0w + (i << 4) + g;
#pragma unroll
        for (int j = 0; j < 8; ++j) {
            int kc = (j << 3) + (q << 1);
            *(float2*)&d2[r0 * 66 + kc]       = make_float2(acc[i][j][0], acc[i][j][1]);
            *(float2*)&d2[(r0 + 8) * 66 + kc] = make_float2(acc[i][j][2], acc[i][j][3]);
        }
    }
    __syncthreads();

    // softmax: one thread per n
    {
        float e[64];
#pragma unroll
        for (int k = 0; k < 64; ++k) e[k] = d2[tid * 66 + k] + cst[k];
        float mn = e[0];
#pragma unroll
        for (int k = 1; k < 64; ++k) mn = fminf(mn, e[k]);
        float s = 0.f;
#pragma unroll
        for (int k = 0; k < 64; ++k) {
            float t = __expf(-0.5f * (e[k] - mn));
            e[k] = t;
            s += t;
        }
        float r = 1.f / s;
        float* sp = sa + (size_t)b * Kq * Nq + n0 + tid;
#pragma unroll
        for (int k = 0; k < 64; ++k) sp[(size_t)k * Nq] = e[k] * r;
    }
}

// ================= w_sum =================
__global__ void wsum_kernel(const float* __restrict__ sa) {
    const int bk = blockIdx.x;      // 1024
    const int tid = threadIdx.x;    // 256
    const float4* row = reinterpret_cast<const float4*>(sa + (size_t)bk * Nq);
    float s = 0.f;
#pragma unroll
    for (int i = 0; i < 4; ++i) {
        float4 v = row[tid + i * 256];
        s += (v.x + v.y) + (v.z + v.w);
    }
#pragma unroll
    for (int off = 16; off; off >>= 1) s += __shfl_xor_sync(0xffffffffu, s, off);
    __shared__ float red[8];
    if ((tid & 31) == 0) red[tid >> 5] = s;
    __syncthreads();
    if (tid == 0) {
        float t = 0.f;
#pragma unroll
        for (int i = 0; i < 8; ++i) t += red[i];
        g_wsum[bk >> 6][bk & 63] = t;
    }
}

// ================= phase 2: wx[c,k] = sum_n x[c,n]*sa[k,n] (3xTF32 mma) =================
// grid (2 ctile, 16 b, 8 seg). block tile 256c x 64k, 32 chunks of 16 n.
__global__ __launch_bounds__(256, 2)
void phase2_kernel(const float* __restrict__ x, const float* __restrict__ sa) {
    extern __shared__ char smem[];
    const int tid = threadIdx.x;
    const int w = tid >> 5, lane = tid & 31;
    const int g = lane >> 2, q = lane & 3;
    const int c0w = w << 5;
    const int c0 = (int)blockIdx.x << 8;
    const int b  = blockIdx.y;
    const int seg = blockIdx.z;
    const int n0 = seg << 9;
    const float* xb = x  + ((size_t)b * Cq + c0) * Nq + n0;
    const float* sb = sa + (size_t)b * Kq * Nq + n0;

    float acc[2][8][4];
#pragma unroll
    for (int i = 0; i < 2; ++i)
#pragma unroll
        for (int j = 0; j < 8; ++j)
#pragma unroll
            for (int e = 0; e < 4; ++e) acc[i][j][e] = 0.f;

    const int n4 = (tid & 3) << 2;
    const int crow = tid >> 2;
    auto fill = [&](int ch, int buf) {
        char* bp = smem + buf * BUF;
        float* aH = (float*)(bp + OFF_FH);
        float* aL = (float*)(bp + OFF_FL);
        float* bH = (float*)(bp + OFF_WH);
        float* bL = (float*)(bp + OFF_WL);
        const int nn = ch << 4;
        // x tile: 256 c rows x 16 n
#pragma unroll
        for (int pz = 0; pz < 4; ++pz) {
            int cc = crow + (pz << 6);
            float4 v = *(const float4*)(xb + (size_t)cc * Nq + nn + n4);
            float vv[4] = { v.x, v.y, v.z, v.w };
            int sz = swz(cc);
#pragma unroll
            for (int e = 0; e < 4; ++e) {
                int nl = n4 + e;
                int p = ((nl >> 3) << 2) + (nl & 3);
                int slot = (nl >> 2) & 1;
                int idx = cc * 16 + ((p ^ sz) << 1) + slot;
                float val = vv[e];
                float h = tf32hi(val);
                aH[idx] = h;
                aL[idx] = val - h;
            }
        }
        // sa tile: 64 k rows x 16 n
        {
            float4 v = *(const float4*)(sb + (size_t)crow * Nq + nn + n4);
            float vv[4] = { v.x, v.y, v.z, v.w };
            int sz = swz(crow);
#pragma unroll
            for (int e = 0; e < 4; ++e) {
                int nl = n4 + e;
                int p = ((nl >> 3) << 2) + (nl & 3);
                int slot = (nl >> 2) & 1;
                int idx = crow * 16 + ((p ^ sz) << 1) + slot;
                float val = vv[e];
                float h = tf32hi(val);
                bH[idx] = h;
                bL[idx] = val - h;
            }
        }
    };

    fill(0, 0);
    __syncthreads();
    for (int ch = 0; ; ++ch) {
        if (ch + 1 < 32) fill(ch + 1, (ch + 1) & 1);
        gemm_chunk(smem + (ch & 1) * BUF, c0w, g, q, acc);
        if (ch + 1 == 32) break;
        __syncthreads();
    }

    // epilogue: scatter D[c,k] partials
    float* basep = &g_wx8[seg][b][0][0];
#pragma unroll
    for (int i = 0; i < 2; ++i) {
        int cc = c0 + c0w + (i << 4) + g;
#pragma unroll
        for (int j = 0; j < 8; ++j) {
            int kc = (j << 3) + (q << 1);
            basep[(size_t)kc * Cq + cc]           = acc[i][j][0];
            basep[(size_t)(kc + 1) * Cq + cc]     = acc[i][j][1];
            basep[(size_t)kc * Cq + cc + 8]       = acc[i][j][2];
            basep[(size_t)(kc + 1) * Cq + cc + 8] = acc[i][j][3];
        }
    }
}

// ================= phase 3: nodes + per-row l2norm =================
__global__ void phase3_kernel(const float* __restrict__ anchor) {
    const int bk = blockIdx.x;     // 1024
    const int b = bk >> 6, k = bk & 63;
    const int tid = threadIdx.x;   // 128
    const float wsv = g_wsum[b][k];
    const float invw = 1.f / (wsv + 1e-9f);
    float t[4];
    float ssq = 0.f;
#pragma unroll
    for (int j = 0; j < 4; ++j) {
        int c = tid + j * 128;
        float wx = 0.f;
#pragma unroll
        for (int s = 0; s < 8; ++s) wx += g_wx8[s][b][k][c];
        float nd = (wx - wsv * anchor[k * Cq + c]) * gInvS[k][c] * invw;
        t[j] = nd;
        ssq += nd * nd;
    }
#pragma unroll
    for (int off = 16; off; off >>= 1) ssq += __shfl_xor_sync(0xffffffffu, ssq, off);
    __shared__ float red[4];
    __shared__ float totsh;
    if ((tid & 31) == 0) red[tid >> 5] = ssq;
    __syncthreads();
    if (tid == 0) totsh = red[0] + red[1] + red[2] + red[3];
    __syncthreads();
    float total = totsh;
    float scale = 1.f / fmaxf(sqrtf(total), 1e-12f);
#pragma unroll
    for (int j = 0; j < 4; ++j) {
        int c = tid + j * 128;
        g_nodes[b][k][c] = t[j] * scale;
    }
    if (tid == 0) g_row[b][k] = total * scale * scale;
}

// ================= phase 4: global l2norm + output =================
__global__ void phase4_kernel(float* __restrict__ outflat) {
    const int b = blockIdx.x;      // 16
    const int tid = threadIdx.x;   // 256
    __shared__ float red[64];
    __shared__ float gsh;
    if (tid < 64) red[tid] = g_row[b][tid];
    __syncthreads();
    if (tid == 0) {
        float s = 0.f;
#pragma unroll
        for (int i = 0; i < 64; ++i) s += red[i];
        gsh = 1.f / fmaxf(sqrtf(s), 1e-12f);
    }
    __syncthreads();
    float g = gsh;
    const float* np = &g_nodes[b][0][0];
    float* op = outflat + (size_t)b * Kq * Cq;
    for (int i = tid; i < Kq * Cq; i += 256) op[i] = np[i] * g;
}

// ================= launch =================
extern "C" void kernel_launch(void* const* d_in, const int* in_sizes, int n_in,
                              void* d_out, int out_size) {
    const float* x      = (const float*)d_in[0];
    const float* anchor = (const float*)d_in[1];
    const float* sraw   = (const float*)d_in[2];
    float* outf = (float*)d_out;

    const int FLAT = Bq * Cq * Kq;      // 524288
    const int SA   = Bq * Kq * Nq;      // 4194304

    float* sa_dev = nullptr;
    cudaGetSymbolAddress((void**)&sa_dev, g_sa);
    float* nodes_dev = nullptr;
    cudaGetSymbolAddress((void**)&nodes_dev, g_nodes);

    float* sa_ptr;
    float* flat_ptr;
    if (out_size == FLAT) {
        flat_ptr = outf;
        sa_ptr = sa_dev;
    } else if (out_size == SA) {
        sa_ptr = outf;
        flat_ptr = nodes_dev;
    } else {
        flat_ptr = outf;
        sa_ptr = outf + FLAT;
    }

    static bool attr_done = false;
    if (!attr_done) {
        cudaFuncSetAttribute(phase1_kernel,
                             cudaFuncAttributeMaxDynamicSharedMemorySize, P_SMEM);
        cudaFuncSetAttribute(phase2_kernel,
                             cudaFuncAttributeMaxDynamicSharedMemorySize, P_SMEM);
        attr_done = true;
    }

    prep_kernel<<<Kq, 256>>>(anchor, sraw);
    phase1_kernel<<<dim3(Nq / 256, Bq), 256, P_SMEM>>>(x, sa_ptr);
    wsum_kernel<<<Bq * Kq, 256>>>(sa_ptr);
    phase2_kernel<<<dim3(Cq / 256, Bq, 8), 256, P_SMEM>>>(x, sa_ptr);
    phase3_kernel<<<Bq * Kq, 128>>>(anchor);
    phase4_kernel<<<Bq, 256>>>(flat_ptr);
}